// round 13
// baseline (speedup 1.0000x reference)
#include <cuda_runtime.h>

#define Bn 256
#define Tn 2048
#define Dn 64
#define LBn 2
#define DBn 32
#define Gn 96
#define Ln 2
#define CH 8      // steps per chunk
#define RD 2      // ring depth in chunks

__device__ float g_dts[Bn * LBn * Tn + 16];
__device__ int   g_cnt[Bn * LBn];

typedef unsigned long long u64;

__device__ __forceinline__ u64 ffma2(u64 a, u64 b, u64 c) {
    u64 d; asm("fma.rn.f32x2 %0,%1,%2,%3;" : "=l"(d) : "l"(a), "l"(b), "l"(c)); return d;
}
__device__ __forceinline__ u64 fadd2(u64 a, u64 b) {
    u64 d; asm("add.rn.f32x2 %0,%1,%2;" : "=l"(d) : "l"(a), "l"(b)); return d;
}
__device__ __forceinline__ float tanha(float x) {
    float y; asm("tanh.approx.f32 %0,%1;" : "=f"(y) : "f"(x)); return y;
}
__device__ __forceinline__ void bar_sync(int id) {
    asm volatile("bar.sync %0, 128;" :: "r"(id) : "memory");
}
__device__ __forceinline__ void bar_arrive(int id) {
    asm volatile("bar.arrive %0, 128;" :: "r"(id) : "memory");
}
__device__ __forceinline__ void membar_cta() {
    asm volatile("membar.cta;" ::: "memory");
}
__device__ __forceinline__ void cbar() { asm volatile("" ::: "memory"); }

// named barrier ids (+slot), count=128 (both band-pairs share each id)
#define B_H1R 1   // r0 -> r2 : h1 chunk ready
#define B_H1F 3   // r2 -> r0 : h1 slot free
#define B_G2R 5   // r2 -> r1 : gx2 chunk ready
#define B_H2R 7   // r1 -> r2 : h2 chunk ready
#define B_H2F 9   // r2 -> r1 : h2 slot free (MLP done)

union F2 { float2 f; u64 u; };
__device__ __forceinline__ u64 pack2(float a, float b) { F2 t; t.f = make_float2(a, b); return t.u; }
__device__ __forceinline__ float hsum(u64 a) { F2 t; t.u = a; return t.f.x + t.f.y; }

__device__ __forceinline__ float dot32i(const u64* w, const u64* hp, float init) {
    u64 a0 = pack2(init, 0.f), a1 = 0ull, a2 = 0ull, a3 = 0ull;
#pragma unroll
    for (int k = 0; k < 16; k += 4) {
        a0 = ffma2(w[k],     hp[k],     a0);
        a1 = ffma2(w[k + 1], hp[k + 1], a1);
        a2 = ffma2(w[k + 2], hp[k + 2], a2);
        a3 = ffma2(w[k + 3], hp[k + 3], a3);
    }
    return hsum(fadd2(fadd2(a0, a1), fadd2(a2, a3)));
}
__device__ __forceinline__ void loadrow(u64* w, const float* p, float s) {
#pragma unroll
    for (int k = 0; k < 16; k++) w[k] = pack2(p[2 * k] * s, p[2 * k + 1] * s);
}
__device__ __forceinline__ void loadhp(u64* hp, const float* row) {
    const ulonglong2* hv = (const ulonglong2*)row;
#pragma unroll
    for (int k = 0; k < 8; k++) { ulonglong2 v = hv[k]; hp[2 * k] = v.x; hp[2 * k + 1] = v.y; }
}

// ---------------------------------------------------------------------------
// Prep: stable compaction of dtime per (row, band) via block prefix scan.
// ---------------------------------------------------------------------------
__global__ void prep_kernel(const int* __restrict__ band_ids,
                            const float* __restrict__ dtime) {
    const int b = blockIdx.x;
    const int tid = threadIdx.x;
    __shared__ int s_scan[256];

    int loc[8]; int cnt = 0;
    const int base = b * Tn + tid * 8;
#pragma unroll
    for (int k = 0; k < 8; k++) { loc[k] = band_ids[base + k]; cnt += loc[k]; }
    s_scan[tid] = cnt;
    __syncthreads();
    for (int off = 1; off < 256; off <<= 1) {
        int v = s_scan[tid];
        int w = (tid >= off) ? s_scan[tid - off] : 0;
        __syncthreads();
        s_scan[tid] = v + w;
        __syncthreads();
    }
    const int total = s_scan[255];
    int ones_before = s_scan[tid] - cnt;
#pragma unroll
    for (int k = 0; k < 8; k++) {
        int t = tid * 8 + k;
        int bid = loc[k];
        int pos = bid ? ones_before : (t - ones_before);
        g_dts[(b * LBn + bid) * Tn + pos] = dtime[b * Tn + t];
        ones_before += bid;
    }
    if (tid == 0) {
        g_cnt[b * LBn + 1] = total;
        g_cnt[b * LBn + 0] = Tn - total;
    }
}

// ---------------------------------------------------------------------------
// Main: 192-thread blocks, 6 warps = 3 roles x 2 band-pairs; each warp drives
// TWO chains of the same band (shared weights in registers, dual streams).
//   role 0: layer-1 recurrence (x2)      -> sH1r ring
//   role 1: layer-2 recurrence (x2)      -> sH2r ring (gx2 from ring)
//   role 2: gx2 = Wih2 @ h1 (x2), MLP head on h2, output, tails
// Block covers b in {2*blk, 2*blk+1}, both bands: 4 chains. grid = 128.
// ---------------------------------------------------------------------------
__global__ void __launch_bounds__(192, 1)
rnn_kernel(const float* __restrict__ zlast,
           const float* __restrict__ projW, const float* __restrict__ projB,
           const float* __restrict__ Wih,   const float* __restrict__ Whh,
           const float* __restrict__ bih,   const float* __restrict__ bhh,
           const float* __restrict__ mW1,   const float* __restrict__ mb1,
           const float* __restrict__ mW2,   const float* __restrict__ mb2,
           float* __restrict__ out) {
    const int tid  = threadIdx.x;
    const int lane = tid & 31;
    const int wid  = tid >> 5;
    const int role = (wid < 3) ? wid : wid - 3;
    const int kb   = (wid >= 3) ? 1 : 0;

    const int bA = blockIdx.x * 2, bB = bA + 1;
    const int cidA = bA * LBn + kb, cidB = bB * LBn + kb;
    const int lcA = kb, lcB = 2 + kb;            // local chain indices

    __shared__ __align__(16) float sH1r[4][RD][CH][32];
    __shared__ __align__(16) float sGX2[4][RD][CH][96];
    __shared__ __align__(16) float sH2r[4][RD][CH][32];
    __shared__ float sBase[4][32], sW[4][32];

    // block-wide chunk count = max chain length in block
    int nmax = 0;
#pragma unroll
    for (int j = 0; j < 4; j++) nmax = max(nmax, g_cnt[blockIdx.x * 4 + j]);
    const int nchT = (nmax + CH - 1) / CH;
    const int nA = g_cnt[cidA], nB = g_cnt[cidB];

    const float* dtsA = g_dts + cidA * Tn;
    const float* dtsB = g_dts + cidB * Tn;
    const int l1 = (kb * Ln + 0) * Gn;
    const int l2 = (kb * Ln + 1) * Gn;

    if (role == 0) {
        // ==== layer-1 recurrence, two chains, shared Whh1 ====
        u64 wr[16], wz[16], wn[16];
        loadrow(wr, &Whh[(l1 + lane) * DBn], 0.5f);
        loadrow(wz, &Whh[(l1 + lane + 32) * DBn], 0.5f);
        loadrow(wn, &Whh[(l1 + lane + 64) * DBn], 1.0f);
        const float bhn1 = bhh[l1 + lane + 64];

        // per-chain collapsed input gates: gx(t) = gb + dt*gw
        float gbr[2], gbz[2], gbn[2], gwr[2], gwz[2], gwn[2];
#pragma unroll
        for (int ch = 0; ch < 2; ch++) {
            const int b  = ch ? bB : bA;
            const int lc = ch ? lcB : lcA;
            float base = projB[kb * DBn + lane];
            float w = projW[(kb * (Dn + 1) + Dn) * DBn + lane];
            for (int i = 0; i < 64; i++)
                base += zlast[b * Dn + i] * projW[(kb * (Dn + 1) + i) * DBn + lane];
            sBase[lc][lane] = base; sW[lc][lane] = w;
            __syncwarp();
            float ar = bih[l1 + lane], cr = 0.f;
            float az = bih[l1 + lane + 32], cz = 0.f;
            float an = bih[l1 + lane + 64], cn = 0.f;
            for (int d = 0; d < 32; d++) {
                float wv = Wih[(l1 + lane) * DBn + d];
                ar += wv * sBase[lc][d]; cr += wv * sW[lc][d];
                wv = Wih[(l1 + lane + 32) * DBn + d];
                az += wv * sBase[lc][d]; cz += wv * sW[lc][d];
                wv = Wih[(l1 + lane + 64) * DBn + d];
                an += wv * sBase[lc][d]; cn += wv * sW[lc][d];
            }
            gbr[ch] = 0.5f * (ar + bhh[l1 + lane]);      gwr[ch] = 0.5f * cr;
            gbz[ch] = 0.5f * (az + bhh[l1 + lane + 32]); gwz[ch] = 0.5f * cz;
            gbn[ch] = an;                                 gwn[ch] = cn;
        }
        // virtual previous slot (chunk -1, slot 1, last step) = zeros
        sH1r[lcA][1][CH - 1][lane] = 0.f;
        sH1r[lcB][1][CH - 1][lane] = 0.f;
        cbar();

        float h1A = 0.f, h1B = 0.f;
        for (int c = 0; c < nchT; c++) {
            const int slot = c & 1, pslot = slot ^ 1;
            if (c >= RD) bar_sync(B_H1F + slot);
#pragma unroll
            for (int i = 0; i < CH; i++) {
                u64 hpA[16], hpB[16];
                const float* prA = (i == 0) ? sH1r[lcA][pslot][CH - 1] : sH1r[lcA][slot][i - 1];
                const float* prB = (i == 0) ? sH1r[lcB][pslot][CH - 1] : sH1r[lcB][slot][i - 1];
                loadhp(hpA, prA);
                loadhp(hpB, prB);
                const float dtA = dtsA[c * CH + i];
                const float dtB = dtsB[c * CH + i];
                float srA  = dot32i(wr, hpA, fmaf(dtA, gwr[0], gbr[0]));
                float srB  = dot32i(wr, hpB, fmaf(dtB, gwr[1], gbr[1]));
                float szA  = dot32i(wz, hpA, fmaf(dtA, gwz[0], gbz[0]));
                float szB  = dot32i(wz, hpB, fmaf(dtB, gwz[1], gbz[1]));
                float ghnA = dot32i(wn, hpA, bhn1);
                float ghnB = dot32i(wn, hpB, bhn1);
                float rA = fmaf(0.5f, tanha(srA), 0.5f);
                float rB = fmaf(0.5f, tanha(srB), 0.5f);
                float zA = fmaf(0.5f, tanha(szA), 0.5f);
                float zB = fmaf(0.5f, tanha(szB), 0.5f);
                float nnA = tanha(fmaf(rA, ghnA, fmaf(dtA, gwn[0], gbn[0])));
                float nnB = tanha(fmaf(rB, ghnB, fmaf(dtB, gwn[1], gbn[1])));
                h1A = fmaf(zA, h1A - nnA, nnA);
                h1B = fmaf(zB, h1B - nnB, nnB);
                sH1r[lcA][slot][i][lane] = h1A;
                sH1r[lcB][slot][i][lane] = h1B;
                cbar();
            }
            membar_cta();
            bar_arrive(B_H1R + slot);
        }
    } else if (role == 1) {
        // ==== layer-2 recurrence, two chains, shared Whh2 ====
        u64 wr[16], wz[16], wn[16];
        loadrow(wr, &Whh[(l2 + lane) * DBn], 0.5f);
        loadrow(wz, &Whh[(l2 + lane + 32) * DBn], 0.5f);
        loadrow(wn, &Whh[(l2 + lane + 64) * DBn], 1.0f);
        const float bhn2 = bhh[l2 + lane + 64];

        sH2r[lcA][1][CH - 1][lane] = 0.f;
        sH2r[lcB][1][CH - 1][lane] = 0.f;
        cbar();

        float h2A = 0.f, h2B = 0.f;
        for (int c = 0; c < nchT; c++) {
            const int slot = c & 1, pslot = slot ^ 1;
            bar_sync(B_G2R + slot);
            if (c >= RD) bar_sync(B_H2F + slot);
#pragma unroll
            for (int i = 0; i < CH; i++) {
                u64 hpA[16], hpB[16];
                const float* prA = (i == 0) ? sH2r[lcA][pslot][CH - 1] : sH2r[lcA][slot][i - 1];
                const float* prB = (i == 0) ? sH2r[lcB][pslot][CH - 1] : sH2r[lcB][slot][i - 1];
                loadhp(hpA, prA);
                loadhp(hpB, prB);
                float gxrA = sGX2[lcA][slot][i][lane];
                float gxrB = sGX2[lcB][slot][i][lane];
                float gxzA = sGX2[lcA][slot][i][lane + 32];
                float gxzB = sGX2[lcB][slot][i][lane + 32];
                float gxnA = sGX2[lcA][slot][i][lane + 64];
                float gxnB = sGX2[lcB][slot][i][lane + 64];
                float srA  = dot32i(wr, hpA, gxrA);
                float srB  = dot32i(wr, hpB, gxrB);
                float szA  = dot32i(wz, hpA, gxzA);
                float szB  = dot32i(wz, hpB, gxzB);
                float ghnA = dot32i(wn, hpA, bhn2);
                float ghnB = dot32i(wn, hpB, bhn2);
                float rA = fmaf(0.5f, tanha(srA), 0.5f);
                float rB = fmaf(0.5f, tanha(srB), 0.5f);
                float zA = fmaf(0.5f, tanha(szA), 0.5f);
                float zB = fmaf(0.5f, tanha(szB), 0.5f);
                float nnA = tanha(fmaf(rA, ghnA, gxnA));
                float nnB = tanha(fmaf(rB, ghnB, gxnB));
                h2A = fmaf(zA, h2A - nnA, nnA);
                h2B = fmaf(zB, h2B - nnB, nnB);
                sH2r[lcA][slot][i][lane] = h2A;
                sH2r[lcB][slot][i][lane] = h2B;
                cbar();
            }
            membar_cta();
            bar_arrive(B_H2R + slot);
        }
    } else {
        // ==== feedforward: gx2 production + MLP head + output, two chains ====
        u64 vr[16], vz[16], vn[16];        // Wih layer2 (r,z half-scaled)
        loadrow(vr, &Wih[(l2 + lane) * DBn], 0.5f);
        loadrow(vz, &Wih[(l2 + lane + 32) * DBn], 0.5f);
        loadrow(vn, &Wih[(l2 + lane + 64) * DBn], 1.0f);
        u64 mcol[16];                      // mW1 column `lane`
#pragma unroll
        for (int k = 0; k < 16; k++)
            mcol[k] = pack2(mW1[kb * 1024 + (2 * k) * 32 + lane],
                            mW1[kb * 1024 + (2 * k + 1) * 32 + lane]);
        const float bir2 = 0.5f * (bih[l2 + lane] + bhh[l2 + lane]);
        const float biz2 = 0.5f * (bih[l2 + lane + 32] + bhh[l2 + lane + 32]);
        const float bin2 = bih[l2 + lane + 64];
        const float mb1v = mb1[kb * DBn + lane];
        const float mw2v = mW2[kb * DBn + lane];
        const float mb2v = mb2[kb];

        float* outA = out + (size_t)(kb * Bn + bA) * Tn;
        float* outB = out + (size_t)(kb * Bn + bB) * Tn;

        // y for h2 == 0 (covers n == 0 chains)
        float y0;
        {
            float m = fmaxf(mb1v, 0.f);
            float y = m * mw2v;
#pragma unroll
            for (int off = 16; off > 0; off >>= 1) y += __shfl_xor_sync(0xffffffffu, y, off);
            y0 = y + mb2v;
        }
        float ylA = y0, ylB = y0;

        for (int c = 0; c < nchT; c++) {
            const int slot = c & 1;
            bar_sync(B_H1R + slot);
#pragma unroll
            for (int i = 0; i < CH; i++) {
                u64 hA[16], hB[16];
                loadhp(hA, sH1r[lcA][slot][i]);
                loadhp(hB, sH1r[lcB][slot][i]);
                sGX2[lcA][slot][i][lane]      = dot32i(vr, hA, bir2);
                sGX2[lcB][slot][i][lane]      = dot32i(vr, hB, bir2);
                sGX2[lcA][slot][i][lane + 32] = dot32i(vz, hA, biz2);
                sGX2[lcB][slot][i][lane + 32] = dot32i(vz, hB, biz2);
                sGX2[lcA][slot][i][lane + 64] = dot32i(vn, hA, bin2);
                sGX2[lcB][slot][i][lane + 64] = dot32i(vn, hB, bin2);
            }
            membar_cta();
            bar_arrive(B_G2R + slot);
            bar_arrive(B_H1F + slot);

            if (c >= 1) {
                const int cc = c - 1, ss = cc & 1;
                bar_sync(B_H2R + ss);
#pragma unroll
                for (int i = 0; i < CH; i++) {
                    const int t = cc * CH + i;
                    u64 hA[16], hB[16];
                    loadhp(hA, sH2r[lcA][ss][i]);
                    loadhp(hB, sH2r[lcB][ss][i]);
                    u64 a0 = 0ull, a1 = 0ull, b0 = 0ull, b1 = 0ull;
#pragma unroll
                    for (int k = 0; k < 16; k += 2) {
                        a0 = ffma2(mcol[k],     hA[k],     a0);
                        a1 = ffma2(mcol[k + 1], hA[k + 1], a1);
                        b0 = ffma2(mcol[k],     hB[k],     b0);
                        b1 = ffma2(mcol[k + 1], hB[k + 1], b1);
                    }
                    float mA = fmaxf(hsum(fadd2(a0, a1)) + mb1v, 0.f);
                    float mB = fmaxf(hsum(fadd2(b0, b1)) + mb1v, 0.f);
                    float yA = mA * mw2v;
                    float yB = mB * mw2v;
#pragma unroll
                    for (int off = 16; off > 0; off >>= 1) {
                        yA += __shfl_xor_sync(0xffffffffu, yA, off);
                        yB += __shfl_xor_sync(0xffffffffu, yB, off);
                    }
                    yA += mb2v; yB += mb2v;
                    if (lane == 0 && t < nA) outA[t] = yA;
                    if (lane == 0 && t < nB) outB[t] = yB;
                    if (t == nA - 1) ylA = yA;
                    if (t == nB - 1) ylB = yB;
                }
                bar_arrive(B_H2F + ss);
            }
        }
        // final MLP chunk
        {
            const int cc = nchT - 1, ss = cc & 1;
            bar_sync(B_H2R + ss);
#pragma unroll
            for (int i = 0; i < CH; i++) {
                const int t = cc * CH + i;
                u64 hA[16], hB[16];
                loadhp(hA, sH2r[lcA][ss][i]);
                loadhp(hB, sH2r[lcB][ss][i]);
                u64 a0 = 0ull, a1 = 0ull, b0 = 0ull, b1 = 0ull;
#pragma unroll
                for (int k = 0; k < 16; k += 2) {
                    a0 = ffma2(mcol[k],     hA[k],     a0);
                    a1 = ffma2(mcol[k + 1], hA[k + 1], a1);
                    b0 = ffma2(mcol[k],     hB[k],     b0);
                    b1 = ffma2(mcol[k + 1], hB[k + 1], b1);
                }
                float mA = fmaxf(hsum(fadd2(a0, a1)) + mb1v, 0.f);
                float mB = fmaxf(hsum(fadd2(b0, b1)) + mb1v, 0.f);
                float yA = mA * mw2v;
                float yB = mB * mw2v;
#pragma unroll
                for (int off = 16; off > 0; off >>= 1) {
                    yA += __shfl_xor_sync(0xffffffffu, yA, off);
                    yB += __shfl_xor_sync(0xffffffffu, yB, off);
                }
                yA += mb2v; yB += mb2v;
                if (lane == 0 && t < nA) outA[t] = yA;
                if (lane == 0 && t < nB) outB[t] = yB;
                if (t == nA - 1) ylA = yA;
                if (t == nB - 1) ylB = yB;
            }
        }
        // tails
        for (int t = nA + lane; t < Tn; t += 32) outA[t] = ylA;
        for (int t = nB + lane; t < Tn; t += 32) outB[t] = ylB;
    }
}

extern "C" void kernel_launch(void* const* d_in, const int* in_sizes, int n_in,
                              void* d_out, int out_size) {
    const int*   band_ids = (const int*)  d_in[0];
    const float* dtime    = (const float*)d_in[1];
    const float* zlast    = (const float*)d_in[2];
    const float* projW    = (const float*)d_in[3];
    const float* projB    = (const float*)d_in[4];
    const float* Wih      = (const float*)d_in[5];
    const float* Whh      = (const float*)d_in[6];
    const float* bihp     = (const float*)d_in[7];
    const float* bhhp     = (const float*)d_in[8];
    const float* mW1      = (const float*)d_in[9];
    const float* mb1      = (const float*)d_in[10];
    const float* mW2      = (const float*)d_in[11];
    const float* mb2      = (const float*)d_in[12];

    prep_kernel<<<Bn, 256>>>(band_ids, dtime);
    rnn_kernel<<<Bn / 2, 192>>>(zlast, projW, projB, Wih, Whh, bihp, bhhp,
                                mW1, mb1, mW2, mb2, (float*)d_out);
}

// round 14
// speedup vs baseline: 2.6175x; 2.6175x over previous
#include <cuda_runtime.h>

#define Bn 256
#define Tn 2048
#define Dn 64
#define LBn 2
#define DBn 32
#define Gn 96
#define Ln 2
#define CH 8      // steps per chunk
#define RD 2      // ring depth in chunks

__device__ float g_dts[Bn * LBn * Tn + 16];
__device__ int   g_cnt[Bn * LBn];

typedef unsigned long long u64;

__device__ __forceinline__ u64 ffma2(u64 a, u64 b, u64 c) {
    u64 d; asm("fma.rn.f32x2 %0,%1,%2,%3;" : "=l"(d) : "l"(a), "l"(b), "l"(c)); return d;
}
__device__ __forceinline__ u64 fadd2(u64 a, u64 b) {
    u64 d; asm("add.rn.f32x2 %0,%1,%2;" : "=l"(d) : "l"(a), "l"(b)); return d;
}
__device__ __forceinline__ float tanha(float x) {
    float y; asm("tanh.approx.f32 %0,%1;" : "=f"(y) : "f"(x)); return y;
}
__device__ __forceinline__ void bar_sync_n(int id, int cnt) {
    asm volatile("bar.sync %0, %1;" :: "r"(id), "r"(cnt) : "memory");
}
__device__ __forceinline__ void bar_arrive_n(int id, int cnt) {
    asm volatile("bar.arrive %0, %1;" :: "r"(id), "r"(cnt) : "memory");
}
__device__ __forceinline__ void membar_cta() {
    asm volatile("membar.cta;" ::: "memory");
}
__device__ __forceinline__ void cbar() { asm volatile("" ::: "memory"); }

union F2 { float2 f; u64 u; };
__device__ __forceinline__ u64 pack2(float a, float b) { F2 t; t.f = make_float2(a, b); return t.u; }
__device__ __forceinline__ float hsum(u64 a) { F2 t; t.u = a; return t.f.x + t.f.y; }

__device__ __forceinline__ float dot32i(const u64* w, const u64* hp, float init) {
    u64 a0 = pack2(init, 0.f), a1 = 0ull, a2 = 0ull, a3 = 0ull;
#pragma unroll
    for (int k = 0; k < 16; k += 4) {
        a0 = ffma2(w[k],     hp[k],     a0);
        a1 = ffma2(w[k + 1], hp[k + 1], a1);
        a2 = ffma2(w[k + 2], hp[k + 2], a2);
        a3 = ffma2(w[k + 3], hp[k + 3], a3);
    }
    return hsum(fadd2(fadd2(a0, a1), fadd2(a2, a3)));
}
__device__ __forceinline__ void loadrow(u64* w, const float* p, float s) {
#pragma unroll
    for (int k = 0; k < 16; k++) w[k] = pack2(p[2 * k] * s, p[2 * k + 1] * s);
}
__device__ __forceinline__ void loadhp(u64* hp, const float* row) {
    const ulonglong2* hv = (const ulonglong2*)row;
#pragma unroll
    for (int k = 0; k < 8; k++) { ulonglong2 v = hv[k]; hp[2 * k] = v.x; hp[2 * k + 1] = v.y; }
}

// ---------------------------------------------------------------------------
// Prep: stable compaction of dtime per (row, band) via block prefix scan.
// ---------------------------------------------------------------------------
__global__ void prep_kernel(const int* __restrict__ band_ids,
                            const float* __restrict__ dtime) {
    const int b = blockIdx.x;
    const int tid = threadIdx.x;
    __shared__ int s_scan[256];

    int loc[8]; int cnt = 0;
    const int base = b * Tn + tid * 8;
#pragma unroll
    for (int k = 0; k < 8; k++) { loc[k] = band_ids[base + k]; cnt += loc[k]; }
    s_scan[tid] = cnt;
    __syncthreads();
    for (int off = 1; off < 256; off <<= 1) {
        int v = s_scan[tid];
        int w = (tid >= off) ? s_scan[tid - off] : 0;
        __syncthreads();
        s_scan[tid] = v + w;
        __syncthreads();
    }
    const int total = s_scan[255];
    int ones_before = s_scan[tid] - cnt;
#pragma unroll
    for (int k = 0; k < 8; k++) {
        int t = tid * 8 + k;
        int bid = loc[k];
        int pos = bid ? ones_before : (t - ones_before);
        g_dts[(b * LBn + bid) * Tn + pos] = dtime[b * Tn + t];
        ones_before += bid;
    }
    if (tid == 0) {
        g_cnt[b * LBn + 1] = total;
        g_cnt[b * LBn + 0] = Tn - total;
    }
}

// ---------------------------------------------------------------------------
// Main: 384-thread blocks, 12 warps = 3 roles x 4 chains.
//   chain = wid & 3 (-> SMSP), role = wid >> 2.
//   r0: layer-1 recurrence (Whh1)           -> sH1r ring (+broadcast)
//   r1: layer-2 recurrence (Whh2)           -> sH2r ring (gx2 from ring)
//   r2: gx2 = Wih2 @ h1 (streamed), MLP head, output, tails
// Named barriers: chains paired {0,1},{2,3}; 4 types x 2 slots x 2 pairs = 16.
//   T1(+0,1) c128: r0 arr -> r2 sync                (h1[slot] ready)
//   T2(+2,3) c192: r2 arr -> r1 sync @c, r0 sync @c+2 (gx2 ready + h1 free)
//   T3(+4,5) c128: r1 arr -> r2 sync @c+1           (h2[slot] ready; gx2 consumed)
//   T4(+6,7) c128: r2 arr -> r1 sync @c+2           (MLP done; h2 slot free)
// Block-wide nchT (max over 4 chains); outputs gated per-chain by n.
// ---------------------------------------------------------------------------
__global__ void __launch_bounds__(384, 1)
rnn_kernel(const float* __restrict__ zlast,
           const float* __restrict__ projW, const float* __restrict__ projB,
           const float* __restrict__ Wih,   const float* __restrict__ Whh,
           const float* __restrict__ bih,   const float* __restrict__ bhh,
           const float* __restrict__ mW1,   const float* __restrict__ mb1,
           const float* __restrict__ mW2,   const float* __restrict__ mb2,
           float* __restrict__ out) {
    const int tid  = threadIdx.x;
    const int lane = tid & 31;
    const int wid  = tid >> 5;
    const int chain = wid & 3;
    const int role  = wid >> 2;

    const int cid = blockIdx.x * 4 + chain;
    const int kb  = cid & 1;
    const int b   = cid >> 1;

    __shared__ __align__(16) float sH1r[4][RD][CH][32];
    __shared__ __align__(16) float sGX2[4][RD][CH][96];
    __shared__ __align__(16) float sH2r[4][RD][CH][32];
    __shared__ __align__(16) float sH1b[4][32];
    __shared__ __align__(16) float sH2b[4][32];
    __shared__ float sBase[4][32], sW[4][32];

    if (role == 0) { sH1b[chain][lane] = 0.f; sH2b[chain][lane] = 0.f; }
    __syncthreads();

    int nmax = 0;
#pragma unroll
    for (int j = 0; j < 4; j++) nmax = max(nmax, g_cnt[blockIdx.x * 4 + j]);
    const int nchT = (nmax + CH - 1) / CH;
    const int n = g_cnt[cid];

    const float* dts = g_dts + cid * Tn;
    const int l1 = (kb * Ln + 0) * Gn;
    const int l2 = (kb * Ln + 1) * Gn;
    const int idbase = (chain >> 1) * 8;
    const int T1 = idbase + 0, T2 = idbase + 2, T3 = idbase + 4, T4 = idbase + 6;

    if (role == 0) {
        // ==== layer-1 recurrence ====
        u64 wr[16], wz[16], wn[16];
        loadrow(wr, &Whh[(l1 + lane) * DBn], 0.5f);
        loadrow(wz, &Whh[(l1 + lane + 32) * DBn], 0.5f);
        loadrow(wn, &Whh[(l1 + lane + 64) * DBn], 1.0f);
        const float bhn1 = bhh[l1 + lane + 64];

        // input projection: x_t = base + dt*w
        float base = projB[kb * DBn + lane];
        float w = projW[(kb * (Dn + 1) + Dn) * DBn + lane];
        for (int i = 0; i < 64; i++)
            base += zlast[b * Dn + i] * projW[(kb * (Dn + 1) + i) * DBn + lane];
        sBase[chain][lane] = base; sW[chain][lane] = w;
        __syncwarp();

        // collapse layer-1 input gates: gx(t) = gb + dt*gw
        float gbr, gbz, gbn, gwr, gwz, gwn;
        {
            float ar = bih[l1 + lane], cr = 0.f;
            float az = bih[l1 + lane + 32], cz = 0.f;
            float an = bih[l1 + lane + 64], cn = 0.f;
            for (int d = 0; d < 32; d++) {
                float wv = Wih[(l1 + lane) * DBn + d];
                ar += wv * sBase[chain][d]; cr += wv * sW[chain][d];
                wv = Wih[(l1 + lane + 32) * DBn + d];
                az += wv * sBase[chain][d]; cz += wv * sW[chain][d];
                wv = Wih[(l1 + lane + 64) * DBn + d];
                an += wv * sBase[chain][d]; cn += wv * sW[chain][d];
            }
            gbr = 0.5f * (ar + bhh[l1 + lane]);      gwr = 0.5f * cr;
            gbz = 0.5f * (az + bhh[l1 + lane + 32]); gwz = 0.5f * cz;
            gbn = an;                                 gwn = cn;
        }

        float h1s = 0.f;
        u64 hp[16];
#pragma unroll
        for (int k = 0; k < 16; k++) hp[k] = 0ull;

        for (int c = 0; c < nchT; c++) {
            const int slot = c & 1;
            if (c >= 2) bar_sync_n(T2 + slot, 192);   // h1[slot] consumed by r2 @ c-2
#pragma unroll
            for (int i = 0; i < CH; i++) {
                const float dt = dts[c * CH + i];
                float sr  = dot32i(wr, hp, fmaf(dt, gwr, gbr));
                float sz  = dot32i(wz, hp, fmaf(dt, gwz, gbz));
                float ghn = dot32i(wn, hp, bhn1);
                float gxn = fmaf(dt, gwn, gbn);
                float r  = fmaf(0.5f, tanha(sr), 0.5f);
                float z  = fmaf(0.5f, tanha(sz), 0.5f);
                float nn = tanha(fmaf(r, ghn, gxn));
                h1s = fmaf(z, h1s - nn, nn);
                sH1b[chain][lane] = h1s;
                cbar();
                loadhp(hp, sH1b[chain]);
                sH1r[chain][slot][i][lane] = h1s;
            }
            membar_cta();
            bar_arrive_n(T1 + slot, 128);
        }
        // close the last two T2 events (r1 waits on them; r0's sync slot is ours)
        bar_arrive_n(T2 + (nchT & 1), 192);
        bar_arrive_n(T2 + ((nchT + 1) & 1), 192);
    } else if (role == 1) {
        // ==== layer-2 recurrence ====
        u64 wr[16], wz[16], wn[16];
        loadrow(wr, &Whh[(l2 + lane) * DBn], 0.5f);
        loadrow(wz, &Whh[(l2 + lane + 32) * DBn], 0.5f);
        loadrow(wn, &Whh[(l2 + lane + 64) * DBn], 1.0f);
        const float bhn2 = bhh[l2 + lane + 64];

        float h2s = 0.f;
        u64 hp[16];
#pragma unroll
        for (int k = 0; k < 16; k++) hp[k] = 0ull;

        for (int c = 0; c < nchT; c++) {
            const int slot = c & 1;
            bar_sync_n(T2 + slot, 192);               // gx2[slot] ready
            if (c >= 2) bar_sync_n(T4 + slot, 128);   // h2[slot] MLP'd by r2
#pragma unroll
            for (int i = 0; i < CH; i++) {
                float gxr = sGX2[chain][slot][i][lane];
                float gxz = sGX2[chain][slot][i][lane + 32];
                float gxn = sGX2[chain][slot][i][lane + 64];
                float sr  = dot32i(wr, hp, gxr);
                float sz  = dot32i(wz, hp, gxz);
                float ghn = dot32i(wn, hp, bhn2);
                float r  = fmaf(0.5f, tanha(sr), 0.5f);
                float z  = fmaf(0.5f, tanha(sz), 0.5f);
                float nn = tanha(fmaf(r, ghn, gxn));
                h2s = fmaf(z, h2s - nn, nn);
                sH2b[chain][lane] = h2s;
                cbar();
                loadhp(hp, sH2b[chain]);
                sH2r[chain][slot][i][lane] = h2s;
            }
            membar_cta();
            bar_arrive_n(T3 + slot, 128);
        }
    } else {
        // ==== feedforward: gx2 (streamed) + MLP head + output + tails ====
        u64 vr[16], vz[16], vn[16];
        loadrow(vr, &Wih[(l2 + lane) * DBn], 0.5f);
        loadrow(vz, &Wih[(l2 + lane + 32) * DBn], 0.5f);
        loadrow(vn, &Wih[(l2 + lane + 64) * DBn], 1.0f);
        u64 mcol[16];
#pragma unroll
        for (int k = 0; k < 16; k++)
            mcol[k] = pack2(mW1[kb * 1024 + (2 * k) * 32 + lane],
                            mW1[kb * 1024 + (2 * k + 1) * 32 + lane]);
        const float bir2 = 0.5f * (bih[l2 + lane] + bhh[l2 + lane]);
        const float biz2 = 0.5f * (bih[l2 + lane + 32] + bhh[l2 + lane + 32]);
        const float bin2 = bih[l2 + lane + 64];
        const float mb1v = mb1[kb * DBn + lane];
        const float mw2v = mW2[kb * DBn + lane];
        const float mb2v = mb2[kb];

        float* outp = out + (size_t)(kb * Bn + b) * Tn;
        float y0;
        {
            float m = fmaxf(mb1v, 0.f);
            float y = m * mw2v;
#pragma unroll
            for (int off = 16; off > 0; off >>= 1) y += __shfl_xor_sync(0xffffffffu, y, off);
            y0 = y + mb2v;
        }
        float yl = y0;

        for (int c = 0; c < nchT; c++) {
            const int slot = c & 1;
            bar_sync_n(T1 + slot, 128);               // h1[slot] ready
#pragma unroll
            for (int i = 0; i < CH; i++) {
                const ulonglong2* hv = (const ulonglong2*)sH1r[chain][slot][i];
                u64 a0 = pack2(bir2, 0.f), a1 = 0ull;
                u64 b0 = pack2(biz2, 0.f), b1 = 0ull;
                u64 c0 = pack2(bin2, 0.f), c1 = 0ull;
#pragma unroll
                for (int k8 = 0; k8 < 8; k8++) {
                    ulonglong2 h = hv[k8];
                    a0 = ffma2(vr[2 * k8], h.x, a0); a1 = ffma2(vr[2 * k8 + 1], h.y, a1);
                    b0 = ffma2(vz[2 * k8], h.x, b0); b1 = ffma2(vz[2 * k8 + 1], h.y, b1);
                    c0 = ffma2(vn[2 * k8], h.x, c0); c1 = ffma2(vn[2 * k8 + 1], h.y, c1);
                }
                sGX2[chain][slot][i][lane]      = hsum(fadd2(a0, a1));
                sGX2[chain][slot][i][lane + 32] = hsum(fadd2(b0, b1));
                sGX2[chain][slot][i][lane + 64] = hsum(fadd2(c0, c1));
            }
            membar_cta();
            bar_arrive_n(T2 + slot, 192);             // gx2 ready + h1 slot free

            if (c >= 1) {
                const int cc = c - 1, ss = cc & 1;
                bar_sync_n(T3 + ss, 128);             // h2[ss] ready
#pragma unroll
                for (int i = 0; i < CH; i++) {
                    const int t = cc * CH + i;
                    const ulonglong2* hv = (const ulonglong2*)sH2r[chain][ss][i];
                    u64 a0 = 0ull, a1 = 0ull;
#pragma unroll
                    for (int k8 = 0; k8 < 8; k8++) {
                        ulonglong2 h = hv[k8];
                        a0 = ffma2(mcol[2 * k8],     h.x, a0);
                        a1 = ffma2(mcol[2 * k8 + 1], h.y, a1);
                    }
                    float m = fmaxf(hsum(fadd2(a0, a1)) + mb1v, 0.f);
                    float y = m * mw2v;
#pragma unroll
                    for (int off = 16; off > 0; off >>= 1) y += __shfl_xor_sync(0xffffffffu, y, off);
                    y += mb2v;
                    if (lane == 0 && t < n) outp[t] = y;
                    if (t == n - 1) yl = y;
                }
                bar_arrive_n(T4 + ss, 128);           // h2 slot free
            }
        }
        // final MLP chunk
        {
            const int cc = nchT - 1, ss = cc & 1;
            bar_sync_n(T3 + ss, 128);
#pragma unroll
            for (int i = 0; i < CH; i++) {
                const int t = cc * CH + i;
                const ulonglong2* hv = (const ulonglong2*)sH2r[chain][ss][i];
                u64 a0 = 0ull, a1 = 0ull;
#pragma unroll
                for (int k8 = 0; k8 < 8; k8++) {
                    ulonglong2 h = hv[k8];
                    a0 = ffma2(mcol[2 * k8],     h.x, a0);
                    a1 = ffma2(mcol[2 * k8 + 1], h.y, a1);
                }
                float m = fmaxf(hsum(fadd2(a0, a1)) + mb1v, 0.f);
                float y = m * mw2v;
#pragma unroll
                for (int off = 16; off > 0; off >>= 1) y += __shfl_xor_sync(0xffffffffu, y, off);
                y += mb2v;
                if (lane == 0 && t < n) outp[t] = y;
                if (t == n - 1) yl = y;
            }
            bar_arrive_n(T4 + ss, 128);
        }
        // tail fill
        for (int t = n + lane; t < Tn; t += 32) outp[t] = yl;
    }
}

extern "C" void kernel_launch(void* const* d_in, const int* in_sizes, int n_in,
                              void* d_out, int out_size) {
    const int*   band_ids = (const int*)  d_in[0];
    const float* dtime    = (const float*)d_in[1];
    const float* zlast    = (const float*)d_in[2];
    const float* projW    = (const float*)d_in[3];
    const float* projB    = (const float*)d_in[4];
    const float* Wih      = (const float*)d_in[5];
    const float* Whh      = (const float*)d_in[6];
    const float* bihp     = (const float*)d_in[7];
    const float* bhhp     = (const float*)d_in[8];
    const float* mW1      = (const float*)d_in[9];
    const float* mb1      = (const float*)d_in[10];
    const float* mW2      = (const float*)d_in[11];
    const float* mb2      = (const float*)d_in[12];

    prep_kernel<<<Bn, 256>>>(band_ids, dtime);
    rnn_kernel<<<Bn / 2, 384>>>(zlast, projW, projB, Wih, Whh, bihp, bhhp,
                                mW1, mb1, mW2, mb2, (float*)d_out);
}

// round 15
// speedup vs baseline: 2.8094x; 1.0733x over previous
#include <cuda_runtime.h>

#define Bn 256
#define Tn 2048
#define Dn 64
#define LBn 2
#define DBn 32
#define Gn 96
#define Ln 2
#define CH 8      // steps per chunk

__device__ float g_dts[Bn * LBn * Tn + 16];
__device__ int   g_cnt[Bn * LBn];

typedef unsigned long long u64;

__device__ __forceinline__ u64 ffma2(u64 a, u64 b, u64 c) {
    u64 d; asm("fma.rn.f32x2 %0,%1,%2,%3;" : "=l"(d) : "l"(a), "l"(b), "l"(c)); return d;
}
__device__ __forceinline__ u64 fadd2(u64 a, u64 b) {
    u64 d; asm("add.rn.f32x2 %0,%1,%2;" : "=l"(d) : "l"(a), "l"(b)); return d;
}
__device__ __forceinline__ float tanha(float x) {
    float y; asm("tanh.approx.f32 %0,%1;" : "=f"(y) : "f"(x)); return y;
}
__device__ __forceinline__ void bar_sync_n(int id, int cnt) {
    asm volatile("bar.sync %0, %1;" :: "r"(id), "r"(cnt) : "memory");
}
__device__ __forceinline__ void cbar() { asm volatile("" ::: "memory"); }

union F2 { float2 f; u64 u; };
__device__ __forceinline__ u64 pack2(float a, float b) { F2 t; t.f = make_float2(a, b); return t.u; }
__device__ __forceinline__ float hsum(u64 a) { F2 t; t.u = a; return t.f.x + t.f.y; }

__device__ __forceinline__ float dot32i(const u64* w, const u64* hp, float init) {
    u64 a0 = pack2(init, 0.f), a1 = 0ull, a2 = 0ull, a3 = 0ull;
#pragma unroll
    for (int k = 0; k < 16; k += 4) {
        a0 = ffma2(w[k],     hp[k],     a0);
        a1 = ffma2(w[k + 1], hp[k + 1], a1);
        a2 = ffma2(w[k + 2], hp[k + 2], a2);
        a3 = ffma2(w[k + 3], hp[k + 3], a3);
    }
    return hsum(fadd2(fadd2(a0, a1), fadd2(a2, a3)));
}
__device__ __forceinline__ void loadrow(u64* w, const float* p, float s) {
#pragma unroll
    for (int k = 0; k < 16; k++) w[k] = pack2(p[2 * k] * s, p[2 * k + 1] * s);
}
__device__ __forceinline__ void loadhp(u64* hp, const float* row) {
    const ulonglong2* hv = (const ulonglong2*)row;
#pragma unroll
    for (int k = 0; k < 8; k++) { ulonglong2 v = hv[k]; hp[2 * k] = v.x; hp[2 * k + 1] = v.y; }
}

// ---------------------------------------------------------------------------
// Prep: stable compaction of dtime per (row, band) via block prefix scan.
// ---------------------------------------------------------------------------
__global__ void prep_kernel(const int* __restrict__ band_ids,
                            const float* __restrict__ dtime) {
    const int b = blockIdx.x;
    const int tid = threadIdx.x;
    __shared__ int s_scan[256];

    int loc[8]; int cnt = 0;
    const int base = b * Tn + tid * 8;
#pragma unroll
    for (int k = 0; k < 8; k++) { loc[k] = band_ids[base + k]; cnt += loc[k]; }
    s_scan[tid] = cnt;
    __syncthreads();
    for (int off = 1; off < 256; off <<= 1) {
        int v = s_scan[tid];
        int w = (tid >= off) ? s_scan[tid - off] : 0;
        __syncthreads();
        s_scan[tid] = v + w;
        __syncthreads();
    }
    const int total = s_scan[255];
    int ones_before = s_scan[tid] - cnt;
#pragma unroll
    for (int k = 0; k < 8; k++) {
        int t = tid * 8 + k;
        int bid = loc[k];
        int pos = bid ? ones_before : (t - ones_before);
        g_dts[(b * LBn + bid) * Tn + pos] = dtime[b * Tn + t];
        ones_before += bid;
    }
    if (tid == 0) {
        g_cnt[b * LBn + 1] = total;
        g_cnt[b * LBn + 0] = Tn - total;
    }
}

// ---------------------------------------------------------------------------
// Main: 384 threads, 12 warps = 3 roles x 4 chains; SMSP = chain = wid & 3.
// TICK-RENDEZVOUS pipeline (per chain, fully decoupled across chains):
//   tick k:  r0 -> h1[k] ;  r2 -> gx2[k-1], MLP/out[k-3] ;  r1 -> h2[k-2]
//   then bar.sync(chain tick id (k&1), 96).  Ticks = nch + 3.
// Depth-2 rings; one STS per h (read back from ring); no membar (bar.sync
// drains STS); 1 barrier op per warp per chunk; per-chain tick counts.
// Barrier ids: chain c uses 8 + 2c + (k&1)  -> ids 8..15.
// ---------------------------------------------------------------------------
__global__ void __launch_bounds__(384, 1)
rnn_kernel(const float* __restrict__ zlast,
           const float* __restrict__ projW, const float* __restrict__ projB,
           const float* __restrict__ Wih,   const float* __restrict__ Whh,
           const float* __restrict__ bih,   const float* __restrict__ bhh,
           const float* __restrict__ mW1,   const float* __restrict__ mb1,
           const float* __restrict__ mW2,   const float* __restrict__ mb2,
           float* __restrict__ out) {
    const int tid  = threadIdx.x;
    const int lane = tid & 31;
    const int wid  = tid >> 5;
    const int chain = wid & 3;
    const int role  = wid >> 2;

    const int cid = blockIdx.x * 4 + chain;
    const int kb  = cid & 1;
    const int b   = cid >> 1;

    __shared__ __align__(16) float sH1r[4][2][CH][32];
    __shared__ __align__(16) float sGX2[4][2][CH][96];
    __shared__ __align__(16) float sH2r[4][2][CH][32];
    __shared__ float sBase[4][32], sW[4][32];

    __syncthreads();   // (barrier 0, full block — before named-bar usage)

    const int n = g_cnt[cid];
    const int nch = (n + CH - 1) / CH;
    const int nticks = nch + 3;
    const float* dts = g_dts + cid * Tn;
    const int l1 = (kb * Ln + 0) * Gn;
    const int l2 = (kb * Ln + 1) * Gn;
    const int tickid = 8 + 2 * chain;

    if (role == 0) {
        // ==== layer-1 recurrence ====
        u64 wr[16], wz[16], wn[16];
        loadrow(wr, &Whh[(l1 + lane) * DBn], 0.5f);
        loadrow(wz, &Whh[(l1 + lane + 32) * DBn], 0.5f);
        loadrow(wn, &Whh[(l1 + lane + 64) * DBn], 1.0f);
        const float bhn1 = bhh[l1 + lane + 64];

        // input projection: x_t = base + dt*w
        float base = projB[kb * DBn + lane];
        float w = projW[(kb * (Dn + 1) + Dn) * DBn + lane];
        for (int i = 0; i < 64; i++)
            base += zlast[b * Dn + i] * projW[(kb * (Dn + 1) + i) * DBn + lane];
        sBase[chain][lane] = base; sW[chain][lane] = w;
        __syncwarp();

        // collapse layer-1 input gates: gx(t) = gb + dt*gw
        float gbr, gbz, gbn, gwr, gwz, gwn;
        {
            float ar = bih[l1 + lane], cr = 0.f;
            float az = bih[l1 + lane + 32], cz = 0.f;
            float an = bih[l1 + lane + 64], cn = 0.f;
            for (int d = 0; d < 32; d++) {
                float wv = Wih[(l1 + lane) * DBn + d];
                ar += wv * sBase[chain][d]; cr += wv * sW[chain][d];
                wv = Wih[(l1 + lane + 32) * DBn + d];
                az += wv * sBase[chain][d]; cz += wv * sW[chain][d];
                wv = Wih[(l1 + lane + 64) * DBn + d];
                an += wv * sBase[chain][d]; cn += wv * sW[chain][d];
            }
            gbr = 0.5f * (ar + bhh[l1 + lane]);      gwr = 0.5f * cr;
            gbz = 0.5f * (az + bhh[l1 + lane + 32]); gwz = 0.5f * cz;
            gbn = an;                                 gwn = cn;
        }

        float h1s = 0.f;
        u64 hp[16];
#pragma unroll
        for (int k = 0; k < 16; k++) hp[k] = 0ull;

        for (int k = 0; k < nticks; k++) {
            const int slot = k & 1;
            if (k < nch) {
#pragma unroll
                for (int i = 0; i < CH; i++) {
                    const float dt = dts[k * CH + i];
                    float sr  = dot32i(wr, hp, fmaf(dt, gwr, gbr));
                    float sz  = dot32i(wz, hp, fmaf(dt, gwz, gbz));
                    float ghn = dot32i(wn, hp, bhn1);
                    float gxn = fmaf(dt, gwn, gbn);
                    float r  = fmaf(0.5f, tanha(sr), 0.5f);
                    float z  = fmaf(0.5f, tanha(sz), 0.5f);
                    float nn = tanha(fmaf(r, ghn, gxn));
                    h1s = fmaf(z, h1s - nn, nn);
                    sH1r[chain][slot][i][lane] = h1s;
                    cbar();                            // warp-sync STS->LDS
                    loadhp(hp, sH1r[chain][slot][i]);
                }
            }
            bar_sync_n(tickid + slot, 96);
        }
    } else if (role == 1) {
        // ==== layer-2 recurrence (chunk k-2 at tick k) ====
        u64 wr[16], wz[16], wn[16];
        loadrow(wr, &Whh[(l2 + lane) * DBn], 0.5f);
        loadrow(wz, &Whh[(l2 + lane + 32) * DBn], 0.5f);
        loadrow(wn, &Whh[(l2 + lane + 64) * DBn], 1.0f);
        const float bhn2 = bhh[l2 + lane + 64];

        float h2s = 0.f;
        u64 hp[16];
#pragma unroll
        for (int k = 0; k < 16; k++) hp[k] = 0ull;

        for (int k = 0; k < nticks; k++) {
            const int ck = k - 2;
            if (ck >= 0 && ck < nch) {
                const int ss = ck & 1;
#pragma unroll
                for (int i = 0; i < CH; i++) {
                    float gxr = sGX2[chain][ss][i][lane];
                    float gxz = sGX2[chain][ss][i][lane + 32];
                    float gxn = sGX2[chain][ss][i][lane + 64];
                    float sr  = dot32i(wr, hp, gxr);
                    float sz  = dot32i(wz, hp, gxz);
                    float ghn = dot32i(wn, hp, bhn2);
                    float r  = fmaf(0.5f, tanha(sr), 0.5f);
                    float z  = fmaf(0.5f, tanha(sz), 0.5f);
                    float nn = tanha(fmaf(r, ghn, gxn));
                    h2s = fmaf(z, h2s - nn, nn);
                    sH2r[chain][ss][i][lane] = h2s;
                    cbar();
                    loadhp(hp, sH2r[chain][ss][i]);
                }
            }
            bar_sync_n(tickid + (k & 1), 96);
        }
    } else {
        // ==== feedforward: gx2 (chunk k-1) + MLP/out (chunk k-3) ====
        u64 vr[16], vz[16], vn[16];
        loadrow(vr, &Wih[(l2 + lane) * DBn], 0.5f);
        loadrow(vz, &Wih[(l2 + lane + 32) * DBn], 0.5f);
        loadrow(vn, &Wih[(l2 + lane + 64) * DBn], 1.0f);
        u64 mcol[16];
#pragma unroll
        for (int k = 0; k < 16; k++)
            mcol[k] = pack2(mW1[kb * 1024 + (2 * k) * 32 + lane],
                            mW1[kb * 1024 + (2 * k + 1) * 32 + lane]);
        const float bir2 = 0.5f * (bih[l2 + lane] + bhh[l2 + lane]);
        const float biz2 = 0.5f * (bih[l2 + lane + 32] + bhh[l2 + lane + 32]);
        const float bin2 = bih[l2 + lane + 64];
        const float mb1v = mb1[kb * DBn + lane];
        const float mw2v = mW2[kb * DBn + lane];
        const float mb2v = mb2[kb];

        float* outp = out + (size_t)(kb * Bn + b) * Tn;
        float y0;
        {
            float m = fmaxf(mb1v, 0.f);
            float y = m * mw2v;
#pragma unroll
            for (int off = 16; off > 0; off >>= 1) y += __shfl_xor_sync(0xffffffffu, y, off);
            y0 = y + mb2v;
        }
        float yl = y0;

        for (int k = 0; k < nticks; k++) {
            const int gk = k - 1;                     // gx2 chunk
            if (gk >= 0 && gk < nch) {
                const int gs = gk & 1;
#pragma unroll
                for (int i = 0; i < CH; i++) {
                    const ulonglong2* hv = (const ulonglong2*)sH1r[chain][gs][i];
                    u64 a0 = pack2(bir2, 0.f), a1 = 0ull;
                    u64 b0 = pack2(biz2, 0.f), b1 = 0ull;
                    u64 c0 = pack2(bin2, 0.f), c1 = 0ull;
#pragma unroll
                    for (int k8 = 0; k8 < 8; k8++) {
                        ulonglong2 h = hv[k8];
                        a0 = ffma2(vr[2 * k8], h.x, a0); a1 = ffma2(vr[2 * k8 + 1], h.y, a1);
                        b0 = ffma2(vz[2 * k8], h.x, b0); b1 = ffma2(vz[2 * k8 + 1], h.y, b1);
                        c0 = ffma2(vn[2 * k8], h.x, c0); c1 = ffma2(vn[2 * k8 + 1], h.y, c1);
                    }
                    sGX2[chain][gs][i][lane]      = hsum(fadd2(a0, a1));
                    sGX2[chain][gs][i][lane + 32] = hsum(fadd2(b0, b1));
                    sGX2[chain][gs][i][lane + 64] = hsum(fadd2(c0, c1));
                }
            }
            const int mk = k - 3;                     // MLP chunk
            if (mk >= 0 && mk < nch) {
                const int ms = mk & 1;
#pragma unroll
                for (int i = 0; i < CH; i++) {
                    const int t = mk * CH + i;
                    const ulonglong2* hv = (const ulonglong2*)sH2r[chain][ms][i];
                    u64 a0 = 0ull, a1 = 0ull;
#pragma unroll
                    for (int k8 = 0; k8 < 8; k8++) {
                        ulonglong2 h = hv[k8];
                        a0 = ffma2(mcol[2 * k8],     h.x, a0);
                        a1 = ffma2(mcol[2 * k8 + 1], h.y, a1);
                    }
                    float m = fmaxf(hsum(fadd2(a0, a1)) + mb1v, 0.f);
                    float y = m * mw2v;
#pragma unroll
                    for (int off = 16; off > 0; off >>= 1) y += __shfl_xor_sync(0xffffffffu, y, off);
                    y += mb2v;
                    if (lane == 0 && t < n) outp[t] = y;
                    if (t == n - 1) yl = y;
                }
            }
            bar_sync_n(tickid + (k & 1), 96);
        }
        // tail fill
        for (int t = n + lane; t < Tn; t += 32) outp[t] = yl;
    }
}

extern "C" void kernel_launch(void* const* d_in, const int* in_sizes, int n_in,
                              void* d_out, int out_size) {
    const int*   band_ids = (const int*)  d_in[0];
    const float* dtime    = (const float*)d_in[1];
    const float* zlast    = (const float*)d_in[2];
    const float* projW    = (const float*)d_in[3];
    const float* projB    = (const float*)d_in[4];
    const float* Wih      = (const float*)d_in[5];
    const float* Whh      = (const float*)d_in[6];
    const float* bihp     = (const float*)d_in[7];
    const float* bhhp     = (const float*)d_in[8];
    const float* mW1      = (const float*)d_in[9];
    const float* mb1      = (const float*)d_in[10];
    const float* mW2      = (const float*)d_in[11];
    const float* mb2      = (const float*)d_in[12];

    prep_kernel<<<Bn, 256>>>(band_ids, dtime);
    rnn_kernel<<<Bn / 2, 384>>>(zlast, projW, projB, Wih, Whh, bihp, bhhp,
                                mW1, mb1, mW2, mb2, (float*)d_out);
}

// round 16
// speedup vs baseline: 3.3470x; 1.1913x over previous
#include <cuda_runtime.h>

#define Bn 256
#define Tn 2048
#define Dn 64
#define LBn 2
#define DBn 32
#define Gn 96
#define Ln 2
#define CH 8      // steps per chunk
#define RD 2      // ring depth in chunks
#define CPB 4     // chains per block

__device__ float g_dts[Bn * LBn * Tn + 16];
__device__ int   g_cnt[Bn * LBn];

typedef unsigned long long u64;

__device__ __forceinline__ u64 ffma2(u64 a, u64 b, u64 c) {
    u64 d; asm("fma.rn.f32x2 %0,%1,%2,%3;" : "=l"(d) : "l"(a), "l"(b), "l"(c)); return d;
}
__device__ __forceinline__ u64 fadd2(u64 a, u64 b) {
    u64 d; asm("add.rn.f32x2 %0,%1,%2;" : "=l"(d) : "l"(a), "l"(b)); return d;
}
__device__ __forceinline__ float tanha(float x) {
    float y; asm("tanh.approx.f32 %0,%1;" : "=f"(y) : "f"(x)); return y;
}
__device__ __forceinline__ void bar_sync(int id) {
    asm volatile("bar.sync %0, 64;" :: "r"(id) : "memory");
}
__device__ __forceinline__ void bar_arrive(int id) {
    asm volatile("bar.arrive %0, 64;" :: "r"(id) : "memory");
}
__device__ __forceinline__ void membar_cta() {
    asm volatile("membar.cta;" ::: "memory");
}
__device__ __forceinline__ void cbar() { asm volatile("" ::: "memory"); }

union F2 { float2 f; u64 u; };
__device__ __forceinline__ u64 pack2(float a, float b) { F2 t; t.f = make_float2(a, b); return t.u; }
__device__ __forceinline__ float hsum(u64 a) { F2 t; t.u = a; return t.f.x + t.f.y; }

// dot of 32 floats (16 f32x2 pairs), scalar init folded, 2 accumulators
__device__ __forceinline__ float dot32i(const u64* w, const u64* hp, float init) {
    u64 a0 = pack2(init, 0.f), a1 = 0ull;
#pragma unroll
    for (int k = 0; k < 16; k += 2) {
        a0 = ffma2(w[k],     hp[k],     a0);
        a1 = ffma2(w[k + 1], hp[k + 1], a1);
    }
    return hsum(fadd2(a0, a1));
}
__device__ __forceinline__ void loadrow(u64* w, const float* p, float s) {
#pragma unroll
    for (int k = 0; k < 16; k++) w[k] = pack2(p[2 * k] * s, p[2 * k + 1] * s);
}
__device__ __forceinline__ void loadhp(u64* hp, const float* row) {
    const ulonglong2* hv = (const ulonglong2*)row;
#pragma unroll
    for (int k = 0; k < 8; k++) { ulonglong2 v = hv[k]; hp[2 * k] = v.x; hp[2 * k + 1] = v.y; }
}

// ---------------------------------------------------------------------------
// Prep: stable compaction of dtime per (row, band) via block prefix scan.
// ---------------------------------------------------------------------------
__global__ void prep_kernel(const int* __restrict__ band_ids,
                            const float* __restrict__ dtime) {
    const int b = blockIdx.x;
    const int tid = threadIdx.x;
    __shared__ int s_scan[256];

    int loc[8]; int cnt = 0;
    const int base = b * Tn + tid * 8;
#pragma unroll
    for (int k = 0; k < 8; k++) { loc[k] = band_ids[base + k]; cnt += loc[k]; }
    s_scan[tid] = cnt;
    __syncthreads();
    for (int off = 1; off < 256; off <<= 1) {
        int v = s_scan[tid];
        int w = (tid >= off) ? s_scan[tid - off] : 0;
        __syncthreads();
        s_scan[tid] = v + w;
        __syncthreads();
    }
    const int total = s_scan[255];
    int ones_before = s_scan[tid] - cnt;
#pragma unroll
    for (int k = 0; k < 8; k++) {
        int t = tid * 8 + k;
        int bid = loc[k];
        int pos = bid ? ones_before : (t - ones_before);
        g_dts[(b * LBn + bid) * Tn + pos] = dtime[b * Tn + t];
        ones_before += bid;
    }
    if (tid == 0) {
        g_cnt[b * LBn + 1] = total;
        g_cnt[b * LBn + 0] = Tn - total;
    }
}

// ---------------------------------------------------------------------------
// Main: 4 chains per 256-thread block (8 warps). chain = wid&3, role = wid>>2.
//   role 0: layer-1 recurrence + gx2 r,z (packed u64) -> sH1r + sGXu rings
//   role 1: layer-2 recurrence + gxn (streamed from h1 ring) + MLP + output
// R10 topology; reg-dieted (streamed ring reads, no manual dt buffers).
// ---------------------------------------------------------------------------
__global__ void __launch_bounds__(256, 1)
rnn_kernel(const float* __restrict__ zlast,
           const float* __restrict__ projW, const float* __restrict__ projB,
           const float* __restrict__ Wih,   const float* __restrict__ Whh,
           const float* __restrict__ bih,   const float* __restrict__ bhh,
           const float* __restrict__ mW1,   const float* __restrict__ mb1,
           const float* __restrict__ mW2,   const float* __restrict__ mb2,
           float* __restrict__ out) {
    const int tid  = threadIdx.x;
    const int lane = tid & 31;
    const int wid  = tid >> 5;
    const int chain = wid & 3;
    const int role  = wid >> 2;

    const int cid = blockIdx.x * CPB + chain;   // == b*LBn + kb
    const int kb  = cid & 1;
    const int b   = cid >> 1;

    __shared__ __align__(16) float sH1r[CPB][RD][CH][32];   // h1 ring
    __shared__ __align__(16) u64   sGXu[CPB][RD][CH][32];   // packed (gxr, gxz) ring
    __shared__ __align__(16) float sH1b[CPB][32];           // role0-private h1 broadcast
    __shared__ __align__(16) float sH2b[CPB][32];           // role1-private h2 broadcast
    __shared__ float sBase[CPB][32], sW[CPB][32], sZ[CPB][64];

    if (role == 0) {
        sZ[chain][lane]      = zlast[b * Dn + lane];
        sZ[chain][lane + 32] = zlast[b * Dn + lane + 32];
        sH1b[chain][lane] = 0.f;
        sH2b[chain][lane] = 0.f;
    }
    __syncthreads();

    const int n = g_cnt[cid];
    const int nch = (n + CH - 1) / CH;
    float* outp = out + (size_t)(kb * Bn + b) * Tn;
    const float* dts = g_dts + cid * Tn;
    const int l1 = (kb * Ln + 0) * Gn;
    const int l2 = (kb * Ln + 1) * Gn;
    const int bRDY = chain * 4;       // +slot : role0 -> role1 (chunk ready)
    const int bFRE = chain * 4 + 2;   // +slot : role1 -> role0 (slot free)

    if (role == 0) {
        // ---- layer-1 recurrence + gx2 r,z production ----
        u64 wr[16], wz[16], wn[16];        // Whh layer1 (r,z half-scaled)
        loadrow(wr, &Whh[(l1 + lane) * DBn], 0.5f);
        loadrow(wz, &Whh[(l1 + lane + 32) * DBn], 0.5f);
        loadrow(wn, &Whh[(l1 + lane + 64) * DBn], 1.0f);
        u64 vr[16], vz[16];                // Wih layer2 r,z (half-scaled)
        loadrow(vr, &Wih[(l2 + lane) * DBn], 0.5f);
        loadrow(vz, &Wih[(l2 + lane + 32) * DBn], 0.5f);
        const float bhn1 = bhh[l1 + lane + 64];
        const float bir2 = 0.5f * (bih[l2 + lane] + bhh[l2 + lane]);
        const float biz2 = 0.5f * (bih[l2 + lane + 32] + bhh[l2 + lane + 32]);

        // input projection: x_t = base + dt*w
        float base = projB[kb * DBn + lane];
        float w = projW[(kb * (Dn + 1) + Dn) * DBn + lane];
#pragma unroll 8
        for (int i = 0; i < 64; i++) base += sZ[chain][i] * projW[(kb * (Dn + 1) + i) * DBn + lane];
        sBase[chain][lane] = base; sW[chain][lane] = w;
        __syncwarp();

        // collapse layer-1 input gates: gx(t) = gb + dt*gw
        float gbr, gbz, gbn, gwr, gwz, gwn;
        {
            float ar = bih[l1 + lane], cr = 0.f;
            float az = bih[l1 + lane + 32], cz = 0.f;
            float an = bih[l1 + lane + 64], cn = 0.f;
#pragma unroll 8
            for (int d = 0; d < 32; d++) {
                float wv = Wih[(l1 + lane) * DBn + d];
                ar += wv * sBase[chain][d]; cr += wv * sW[chain][d];
                wv = Wih[(l1 + lane + 32) * DBn + d];
                az += wv * sBase[chain][d]; cz += wv * sW[chain][d];
                wv = Wih[(l1 + lane + 64) * DBn + d];
                an += wv * sBase[chain][d]; cn += wv * sW[chain][d];
            }
            gbr = 0.5f * (ar + bhh[l1 + lane]);      gwr = 0.5f * cr;
            gbz = 0.5f * (az + bhh[l1 + lane + 32]); gwz = 0.5f * cz;
            gbn = an;                                 gwn = cn;
        }

        float h1s = 0.f;
        u64 hp[16];
#pragma unroll
        for (int k = 0; k < 16; k++) hp[k] = 0ull;

        for (int c = 0; c < nch; c++) {
            const int slot = c & 1;
            if (c >= RD) bar_sync(bFRE + slot);        // wait: role1 freed slot
#pragma unroll
            for (int i = 0; i < CH; i++) {
                const float dt = dts[c * CH + i];
                // layer-1 recurrence (critical chain)
                float sr  = dot32i(wr, hp, fmaf(dt, gwr, gbr));
                float sz  = dot32i(wz, hp, fmaf(dt, gwz, gbz));
                float ghn = dot32i(wn, hp, bhn1);
                float gxn = fmaf(dt, gwn, gbn);
                float r  = fmaf(0.5f, tanha(sr), 0.5f);
                float z  = fmaf(0.5f, tanha(sz), 0.5f);
                float nn = tanha(fmaf(r, ghn, gxn));
                h1s = fmaf(z, h1s - nn, nn);
                sH1b[chain][lane] = h1s;
                cbar();                                 // warp-synchronous STS->LDS
                loadhp(hp, sH1b[chain]);
                // publish h1 + packed gx2 r,z (off-chain)
                sH1r[chain][slot][i][lane] = h1s;
                sGXu[chain][slot][i][lane] =
                    pack2(dot32i(vr, hp, bir2), dot32i(vz, hp, biz2));
            }
            membar_cta();
            bar_arrive(bRDY + slot);                   // signal: chunk ready
        }
    } else {
        // ---- layer-2 recurrence + gxn + MLP head + output ----
        u64 wr[16], wz[16], wn[16];        // Whh layer2 (r,z half-scaled)
        loadrow(wr, &Whh[(l2 + lane) * DBn], 0.5f);
        loadrow(wz, &Whh[(l2 + lane + 32) * DBn], 0.5f);
        loadrow(wn, &Whh[(l2 + lane + 64) * DBn], 1.0f);
        u64 vn[16];                        // Wih layer2 n-gate (full scale)
        loadrow(vn, &Wih[(l2 + lane + 64) * DBn], 1.0f);
        u64 mcol[16];                      // mW1 column `lane`
#pragma unroll
        for (int k = 0; k < 16; k++)
            mcol[k] = pack2(mW1[kb * 1024 + (2 * k) * 32 + lane],
                            mW1[kb * 1024 + (2 * k + 1) * 32 + lane]);
        const float bhn2 = bhh[l2 + lane + 64];
        const float bin2 = bih[l2 + lane + 64];
        const float mb1v = mb1[kb * DBn + lane];
        const float mw2v = mW2[kb * DBn + lane];
        const float mb2v = mb2[kb];
        float yl = 0.f;

        float h2s = 0.f;
        u64 hp[16];
#pragma unroll
        for (int k = 0; k < 16; k++) hp[k] = 0ull;

        for (int c = 0; c < nch; c++) {
            const int slot = c & 1;
            bar_sync(bRDY + slot);                     // wait: chunk ready
#pragma unroll
            for (int i = 0; i < CH; i++) {
                const int t = c * CH + i;
                // gxn from h1 ring (streamed window, off the h2 critical chain)
                float gxn;
                {
                    const ulonglong2* hv = (const ulonglong2*)sH1r[chain][slot][i];
                    u64 c0 = pack2(bin2, 0.f), c1 = 0ull;
#pragma unroll
                    for (int k8 = 0; k8 < 8; k8++) {
                        ulonglong2 h = hv[k8];
                        c0 = ffma2(vn[2 * k8],     h.x, c0);
                        c1 = ffma2(vn[2 * k8 + 1], h.y, c1);
                    }
                    gxn = hsum(fadd2(c0, c1));
                }
                F2 g; g.u = sGXu[chain][slot][i][lane];
                // layer-2 recurrence (critical chain)
                float sr  = dot32i(wr, hp, g.f.x);
                float sz  = dot32i(wz, hp, g.f.y);
                float ghn = dot32i(wn, hp, bhn2);
                float r  = fmaf(0.5f, tanha(sr), 0.5f);
                float z  = fmaf(0.5f, tanha(sz), 0.5f);
                float nn = tanha(fmaf(r, ghn, gxn));
                h2s = fmaf(z, h2s - nn, nn);
                sH2b[chain][lane] = h2s;
                cbar();
                loadhp(hp, sH2b[chain]);
                // MLP head (off-chain ILP), mW1 column in registers
                u64 a0 = 0ull, a1 = 0ull;
#pragma unroll
                for (int k = 0; k < 16; k += 2) {
                    a0 = ffma2(mcol[k],     hp[k],     a0);
                    a1 = ffma2(mcol[k + 1], hp[k + 1], a1);
                }
                float m = fmaxf(hsum(fadd2(a0, a1)) + mb1v, 0.f);
                float y = m * mw2v;
#pragma unroll
                for (int off = 16; off > 0; off >>= 1) y += __shfl_xor_sync(0xffffffffu, y, off);
                y += mb2v;
                if (lane == 0 && t < n) outp[t] = y;
                if (t == n - 1) yl = y;
            }
            bar_arrive(bFRE + slot);                   // signal: slot free
        }
        if (n == 0) {
            float m = fmaxf(mb1v, 0.f);
            float y = m * mw2v;
#pragma unroll
            for (int off = 16; off > 0; off >>= 1) y += __shfl_xor_sync(0xffffffffu, y, off);
            yl = y + mb2v;
        }
        for (int t = n + lane; t < Tn; t += 32) outp[t] = yl;
    }
}

extern "C" void kernel_launch(void* const* d_in, const int* in_sizes, int n_in,
                              void* d_out, int out_size) {
    const int*   band_ids = (const int*)  d_in[0];
    const float* dtime    = (const float*)d_in[1];
    const float* zlast    = (const float*)d_in[2];
    const float* projW    = (const float*)d_in[3];
    const float* projB    = (const float*)d_in[4];
    const float* Wih      = (const float*)d_in[5];
    const float* Whh      = (const float*)d_in[6];
    const float* bihp     = (const float*)d_in[7];
    const float* bhhp     = (const float*)d_in[8];
    const float* mW1      = (const float*)d_in[9];
    const float* mb1      = (const float*)d_in[10];
    const float* mW2      = (const float*)d_in[11];
    const float* mb2      = (const float*)d_in[12];

    prep_kernel<<<Bn, 256>>>(band_ids, dtime);
    rnn_kernel<<<(Bn * LBn) / CPB, 256>>>(zlast, projW, projB, Wih, Whh, bihp, bhhp,
                                          mW1, mb1, mW2, mb2, (float*)d_out);
}